// round 15
// baseline (speedup 1.0000x reference)
#include <cuda_runtime.h>
#include <cstdint>

// ===========================================================================
// Problem constants
// ===========================================================================
namespace {
constexpr int kB  = 2;
constexpr int kS  = 2048;
constexpr int kD  = 1024;
constexpr int kH  = 16;
constexpr int kDK = 64;
constexpr int kBH = kB * kH;        // 32
constexpr int kBS = kB * kS;        // 4096
constexpr int kNRows = kBH * kS;    // 65536

// proj smem: Ah/Al/Bh/Bl [128 rows][36 floats]
constexpr int kPRS   = 36;
constexpr int kPTile = 128 * kPRS;
constexpr int kPSmem = 4 * kPTile * 4;             // 73728 bytes

// scores smem: Qh/Ql [128][68] + Kh/Kl [64][68]
constexpr int kQRS   = 68;
constexpr int kQTile = 128 * kQRS;
constexpr int kKTile = 64 * kQRS;
constexpr int kSSmem = (2 * kQTile + 2 * kKTile) * 4;   // 104448 bytes
}

// Scratch (allocation-free rule: __device__ globals)
__device__ float g_q [kBH * kS * kDK];   // 16 MB
__device__ float g_kr[kBH * kS * kDK];   // 16 MB (k_proj + r_proj)
__device__ float g_v [kBH * kS * kDK];   // 16 MB
__device__ float g_rinv[kNRows];

// ===========================================================================
// helpers (arch-neutral PTX, valid on sm_100 target)
// ===========================================================================
__device__ __forceinline__ void split_tf32(float x, uint32_t& hi, uint32_t& lo) {
    uint32_t h;
    asm("cvt.rna.tf32.f32 %0, %1;" : "=r"(h) : "f"(x));
    float lf = x - __uint_as_float(h);
    uint32_t l;
    asm("cvt.rna.tf32.f32 %0, %1;" : "=r"(l) : "f"(lf));
    hi = h; lo = l;
}

// D += A(tf32) * B(tf32); m16n8k8, A row-major, B col-major.
__device__ __forceinline__ void mma_m16n8k8_tf32(float* d, const uint32_t* a,
                                                 const uint32_t* b) {
    asm volatile(
        "mma.sync.aligned.m16n8k8.row.col.f32.tf32.tf32.f32 "
        "{%0,%1,%2,%3}, {%4,%5,%6,%7}, {%8,%9}, {%0,%1,%2,%3};"
        : "+f"(d[0]), "+f"(d[1]), "+f"(d[2]), "+f"(d[3])
        : "r"(a[0]), "r"(a[1]), "r"(a[2]), "r"(a[3]), "r"(b[0]), "r"(b[1]));
}

__device__ __forceinline__ void ldsm_x4(uint32_t* r, uint32_t saddr) {
    asm volatile("ldmatrix.sync.aligned.m8n8.x4.shared.b16 {%0,%1,%2,%3}, [%4];"
        : "=r"(r[0]), "=r"(r[1]), "=r"(r[2]), "=r"(r[3]) : "r"(saddr));
}
__device__ __forceinline__ void ldsm_x2(uint32_t* r, uint32_t saddr) {
    asm volatile("ldmatrix.sync.aligned.m8n8.x2.shared.b16 {%0,%1}, [%2];"
        : "=r"(r[0]), "=r"(r[1]) : "r"(saddr));
}
__device__ __forceinline__ uint32_t smem_u32(const void* p) {
    return (uint32_t)__cvta_generic_to_shared(p);
}

// ===========================================================================
// MERGED projection GEMM via mma.sync tf32x3 + ldmatrix.
// grid (D/128, BS/128, 3): z=0 -> q (query*Wq), z=1 -> kr (key*Wk + r*Wr),
// z=2 -> v (value*Wv). One launch packs all 768 CTAs into the SM pool
// (vs 3 serial underfilled waves).
// ===========================================================================
__global__ __launch_bounds__(256) void proj_mma_kernel(
    const float* __restrict__ query, const float* __restrict__ Wq, const float* __restrict__ bq,
    const float* __restrict__ key,   const float* __restrict__ Wk, const float* __restrict__ bk,
    const float* __restrict__ r,     const float* __restrict__ Wr, const float* __restrict__ br,
    const float* __restrict__ value, const float* __restrict__ Wv, const float* __restrict__ bv)
{
    extern __shared__ uint32_t smem_u[];
    uint32_t* Ah = smem_u;
    uint32_t* Al = smem_u + kPTile;
    uint32_t* Bh = smem_u + 2 * kPTile;
    uint32_t* Bl = smem_u + 3 * kPTile;
    const uint32_t ah_b = smem_u32(Ah), al_b = smem_u32(Al);
    const uint32_t bh_b = smem_u32(Bh), bl_b = smem_u32(Bl);

    const int zsel = blockIdx.z;
    const float* X1; const float* W1; const float* b1;
    const float* X2 = nullptr; const float* W2 = nullptr; const float* b2 = nullptr;
    int ns;
    if (zsel == 0)      { X1 = query; W1 = Wq; b1 = bq; ns = 32; }
    else if (zsel == 1) { X1 = key;   W1 = Wk; b1 = bk;
                          X2 = r;     W2 = Wr; b2 = br; ns = 64; }
    else                { X1 = value; W1 = Wv; b1 = bv; ns = 32; }

    const int tid   = threadIdx.x;
    const int wid   = tid >> 5;
    const int lane  = tid & 31;
    const int gid   = lane >> 2;
    const int tid4  = lane & 3;
    const int wm    = (wid >> 2) * 64;
    const int wn    = (wid & 3) * 32;
    const int m0    = blockIdx.y * 128;
    const int n0    = blockIdx.x * 128;

    const int a_row = lane & 15;
    const int a_ko  = ((lane >> 4) & 1) << 2;
    const int b_row = lane & 7;
    const int b_ko  = ((lane >> 3) & 1) << 2;

    float acc[4][4][4];
#pragma unroll
    for (int mt = 0; mt < 4; ++mt)
#pragma unroll
        for (int nt = 0; nt < 4; ++nt)
#pragma unroll
            for (int f = 0; f < 4; ++f) acc[mt][nt][f] = 0.f;

    for (int s = 0; s < ns; ++s) {
        const float* __restrict__ X = (s < 32) ? X1 : X2;
        const float* __restrict__ W = (s < 32) ? W1 : W2;
        const int k0 = (s & 31) * 32;

        float4 xa[4], wb[4];
#pragma unroll
        for (int i = 0; i < 4; ++i) {
            const int idx = tid + 256 * i;
            const int row = idx >> 3;
            const int c4  = (idx & 7) * 4;
            xa[i] = *reinterpret_cast<const float4*>(&X[(size_t)(m0 + row) * kD + k0 + c4]);
            wb[i] = *reinterpret_cast<const float4*>(&W[(size_t)(n0 + row) * kD + k0 + c4]);
        }
        __syncthreads();
#pragma unroll
        for (int i = 0; i < 4; ++i) {
            const int idx = tid + 256 * i;
            const int row = idx >> 3;
            const int c4  = (idx & 7) * 4;
            const float* xv = reinterpret_cast<const float*>(&xa[i]);
            const float* wv = reinterpret_cast<const float*>(&wb[i]);
#pragma unroll
            for (int j = 0; j < 4; ++j) {
                uint32_t h, l;
                split_tf32(xv[j], h, l);
                Ah[row * kPRS + c4 + j] = h;
                Al[row * kPRS + c4 + j] = l;
                split_tf32(wv[j], h, l);
                Bh[row * kPRS + c4 + j] = h;
                Bl[row * kPRS + c4 + j] = l;
            }
        }
        __syncthreads();

#pragma unroll
        for (int kk = 0; kk < 4; ++kk) {
            const int kb = kk * 8;

            uint32_t bhf[4][2], blf[4][2];
#pragma unroll
            for (int nt = 0; nt < 4; ++nt) {
                const uint32_t off =
                    (uint32_t)(((wn + nt * 8 + b_row) * kPRS + kb + b_ko) * 4);
                ldsm_x2(bhf[nt], bh_b + off);
                ldsm_x2(blf[nt], bl_b + off);
            }

#pragma unroll
            for (int mt = 0; mt < 4; ++mt) {
                const uint32_t off =
                    (uint32_t)(((wm + mt * 16 + a_row) * kPRS + kb + a_ko) * 4);
                uint32_t ah[4], al[4];
                ldsm_x4(ah, ah_b + off);
                ldsm_x4(al, al_b + off);
#pragma unroll
                for (int nt = 0; nt < 4; ++nt) {
                    mma_m16n8k8_tf32(acc[mt][nt], ah, bhf[nt]);
                    mma_m16n8k8_tf32(acc[mt][nt], ah, blf[nt]);
                    mma_m16n8k8_tf32(acc[mt][nt], al, bhf[nt]);
                }
            }
        }
    }

    float* __restrict__ dst = (zsel == 0) ? g_q : (zsel == 1) ? g_kr : g_v;
#pragma unroll
    for (int nt = 0; nt < 4; ++nt) {
        const int e  = n0 + wn + nt * 8 + 2 * tid4;
        const int h  = e >> 6;
        const int dk = e & 63;
        float2 bb;
        bb.x = b1[e];     bb.y = b1[e + 1];
        if (X2) { bb.x += b2[e]; bb.y += b2[e + 1]; }
#pragma unroll
        for (int mt = 0; mt < 4; ++mt) {
#pragma unroll
            for (int half = 0; half < 2; ++half) {
                const int gm   = m0 + wm + mt * 16 + gid + half * 8;
                const int bidx = gm >> 11;
                const int srow = gm & (kS - 1);
                float2 o;
                o.x = acc[mt][nt][half * 2 + 0] + bb.x;
                o.y = acc[mt][nt][half * 2 + 1] + bb.y;
                *reinterpret_cast<float2*>(
                    &dst[(((size_t)bidx * kH + h) * kS + srow) * kDK + dk]) = o;
            }
        }
    }
}

// ===========================================================================
// Fused scores + softmax numerator + row sums via mma.sync tf32x3 + ldmatrix.
// (R11 verbatim, measured 489us)
// ===========================================================================
__global__ __launch_bounds__(256, 2) void scores_mma_kernel(const int* __restrict__ mask,
                                                            float* __restrict__ p)
{
    extern __shared__ uint32_t smem_u[];
    uint32_t* Qh = smem_u;
    uint32_t* Ql = smem_u + kQTile;
    uint32_t* Kh = smem_u + 2 * kQTile;
    uint32_t* Kl = smem_u + 2 * kQTile + kKTile;
    const uint32_t qh_b = smem_u32(Qh), ql_b = smem_u32(Ql);
    const uint32_t kh_b = smem_u32(Kh), kl_b = smem_u32(Kl);
    __shared__ float rs[128];

    const int tid   = threadIdx.x;
    const int wid   = tid >> 5;
    const int lane  = tid & 31;
    const int gid   = lane >> 2;
    const int tid4  = lane & 3;
    const int wm    = (wid >> 2) * 64;
    const int wn    = (wid & 3) * 16;
    const int bh    = blockIdx.y;
    const int m0    = blockIdx.x * 128;
    const int b_    = bh >> 4;
    const float scale = 0.125f;

    const int a_row = lane & 15;
    const int a_ko  = ((lane >> 4) & 1) << 2;
    const int b_row = lane & 7;
    const int b_ko  = ((lane >> 3) & 1) << 2;

    const float* __restrict__ Q  = g_q  + (size_t)bh * kS * kDK;
    const float* __restrict__ KR = g_kr + (size_t)bh * kS * kDK;

    if (tid < 128) rs[tid] = 0.f;

    for (int i = tid; i < 128 * 16; i += 256) {
        const int row = i >> 4;
        const int kq  = (i & 15) * 4;
        float4 v = *reinterpret_cast<const float4*>(&Q[(size_t)(m0 + row) * kDK + kq]);
        const float* vv = reinterpret_cast<const float*>(&v);
#pragma unroll
        for (int j = 0; j < 4; ++j) {
            uint32_t h, l;
            split_tf32(vv[j], h, l);
            Qh[row * kQRS + kq + j] = h;
            Ql[row * kQRS + kq + j] = l;
        }
    }

    float rsum[4][2];
#pragma unroll
    for (int mt = 0; mt < 4; ++mt) { rsum[mt][0] = 0.f; rsum[mt][1] = 0.f; }

    for (int nb = 0; nb < kS; nb += 64) {
        __syncthreads();
        for (int i = tid; i < 64 * 16; i += 256) {
            const int n  = i >> 4;
            const int kq = (i & 15) * 4;
            float4 v = *reinterpret_cast<const float4*>(&KR[(size_t)(nb + n) * kDK + kq]);
            const float* vv = reinterpret_cast<const float*>(&v);
#pragma unroll
            for (int j = 0; j < 4; ++j) {
                uint32_t h, l;
                split_tf32(vv[j], h, l);
                Kh[n * kQRS + kq + j] = h;
                Kl[n * kQRS + kq + j] = l;
            }
        }
        __syncthreads();

        float acc[4][2][4];
#pragma unroll
        for (int mt = 0; mt < 4; ++mt)
#pragma unroll
            for (int nt = 0; nt < 2; ++nt)
#pragma unroll
                for (int f = 0; f < 4; ++f) acc[mt][nt][f] = 0.f;

#pragma unroll
        for (int kk = 0; kk < 8; ++kk) {
            const int kb = kk * 8;

            uint32_t bhf[2][2], blf[2][2];
#pragma unroll
            for (int nt = 0; nt < 2; ++nt) {
                const uint32_t off =
                    (uint32_t)(((wn + nt * 8 + b_row) * kQRS + kb + b_ko) * 4);
                ldsm_x2(bhf[nt], kh_b + off);
                ldsm_x2(blf[nt], kl_b + off);
            }

#pragma unroll
            for (int mt = 0; mt < 4; ++mt) {
                const uint32_t off =
                    (uint32_t)(((wm + mt * 16 + a_row) * kQRS + kb + a_ko) * 4);
                uint32_t ah[4], al[4];
                ldsm_x4(ah, qh_b + off);
                ldsm_x4(al, ql_b + off);
#pragma unroll
                for (int nt = 0; nt < 2; ++nt) {
                    mma_m16n8k8_tf32(acc[mt][nt], ah, bhf[nt]);
                    mma_m16n8k8_tf32(acc[mt][nt], ah, blf[nt]);
                    mma_m16n8k8_tf32(acc[mt][nt], al, bhf[nt]);
                }
            }
        }

#pragma unroll
        for (int mt = 0; mt < 4; ++mt) {
#pragma unroll
            for (int nt = 0; nt < 2; ++nt) {
                const int sk = nb + wn + nt * 8 + 2 * tid4;
#pragma unroll
                for (int half = 0; half < 2; ++half) {
                    const int sq = m0 + wm + mt * 16 + gid + half * 8;
                    int2 mm = *reinterpret_cast<const int2*>(
                        &mask[((size_t)b_ * kS + sq) * kS + sk]);
                    const float f0 = acc[mt][nt][half * 2 + 0] * scale;
                    const float f1 = acc[mt][nt][half * 2 + 1] * scale;
                    float2 e;
                    e.x = mm.x ? __expf(f0) : 0.f;
                    e.y = mm.y ? __expf(f1) : 0.f;
                    *reinterpret_cast<float2*>(
                        &p[((size_t)bh * kS + sq) * kS + sk]) = e;
                    rsum[mt][half] += e.x + e.y;
                }
            }
        }
    }

    __syncthreads();
#pragma unroll
    for (int mt = 0; mt < 4; ++mt) {
#pragma unroll
        for (int half = 0; half < 2; ++half) {
            float s = rsum[mt][half];
            s += __shfl_xor_sync(0xffffffffu, s, 1);
            s += __shfl_xor_sync(0xffffffffu, s, 2);
            if (tid4 == 0)
                atomicAdd(&rs[wm + mt * 16 + gid + half * 8], s);
        }
    }
    __syncthreads();
    if (tid < 128) g_rinv[bh * kS + m0 + tid] = 1.0f / rs[tid];
}

// ===========================================================================
// out = p @ v with on-the-fly normalization; writes final p back.
// R8 version verbatim (measured ~453us; best of 4 variants tried).
// ===========================================================================
__global__ __launch_bounds__(256, 2) void out_kernel(float* __restrict__ p,
                                                     float* __restrict__ out)
{
    __shared__ float As[16][128];
    __shared__ float Bs[16][64];
    __shared__ float s_inv[128];

    const int bh  = blockIdx.y;
    const int m0  = blockIdx.x * 128;
    const int tid = threadIdx.x;
    const int tx  = tid & 15;
    const int ty  = tid >> 4;

    if (tid < 128) {
        s_inv[tid] = g_rinv[bh * kS + m0 + tid];
    }
    __syncthreads();

    float acc[8][4];
#pragma unroll
    for (int i = 0; i < 8; ++i)
#pragma unroll
        for (int j = 0; j < 4; ++j) acc[i][j] = 0.f;

    float* __restrict__ prow = p + (size_t)bh * kS * kS + (size_t)m0 * kS;
    const float* __restrict__ V = g_v + (size_t)bh * kS * kDK;

    const int r0 = tid >> 2;
    const int c0 = (tid & 3) * 4;
    const int vk = tid >> 4;
    const int vn = (tid & 15) * 4;

    const float iv0 = s_inv[r0];
    const float iv1 = s_inv[r0 + 64];

    for (int k0 = 0; k0 < kS; k0 += 16) {
        float4 x0 = *reinterpret_cast<const float4*>(&prow[(size_t)r0 * kS + k0 + c0]);
        float4 x1 = *reinterpret_cast<const float4*>(&prow[(size_t)(r0 + 64) * kS + k0 + c0]);
        float4 n0v, n1v;
        n0v.x = x0.x * iv0;  n0v.y = x0.y * iv0;
        n0v.z = x0.z * iv0;  n0v.w = x0.w * iv0;
        n1v.x = x1.x * iv1;  n1v.y = x1.y * iv1;
        n1v.z = x1.z * iv1;  n1v.w = x1.w * iv1;

        float4 vb = *reinterpret_cast<const float4*>(&V[(k0 + vk) * kDK + vn]);

        __syncthreads();
        As[c0 + 0][r0]      = n0v.x; As[c0 + 1][r0]      = n0v.y;
        As[c0 + 2][r0]      = n0v.z; As[c0 + 3][r0]      = n0v.w;
        As[c0 + 0][r0 + 64] = n1v.x; As[c0 + 1][r0 + 64] = n1v.y;
        As[c0 + 2][r0 + 64] = n1v.z; As[c0 + 3][r0 + 64] = n1v.w;
        *reinterpret_cast<float4*>(&Bs[vk][vn]) = vb;

        *reinterpret_cast<float4*>(&prow[(size_t)r0 * kS + k0 + c0])        = n0v;
        *reinterpret_cast<float4*>(&prow[(size_t)(r0 + 64) * kS + k0 + c0]) = n1v;
        __syncthreads();

#pragma unroll
        for (int kk = 0; kk < 16; ++kk) {
            float4 a0 = *reinterpret_cast<const float4*>(&As[kk][ty * 8]);
            float4 a1 = *reinterpret_cast<const float4*>(&As[kk][ty * 8 + 4]);
            float4 bb = *reinterpret_cast<const float4*>(&Bs[kk][tx * 4]);
            float a[8]  = {a0.x, a0.y, a0.z, a0.w, a1.x, a1.y, a1.z, a1.w};
            float bj[4] = {bb.x, bb.y, bb.z, bb.w};
#pragma unroll
            for (int i = 0; i < 8; ++i)
#pragma unroll
                for (int j = 0; j < 4; ++j) acc[i][j] += a[i] * bj[j];
        }
    }

    float* __restrict__ orow = out + (size_t)bh * kS * kDK;
#pragma unroll
    for (int i = 0; i < 8; ++i) {
        float4 o = make_float4(acc[i][0], acc[i][1], acc[i][2], acc[i][3]);
        *reinterpret_cast<float4*>(&orow[(m0 + ty * 8 + i) * kDK + tx * 4]) = o;
    }
}

// ===========================================================================
extern "C" void kernel_launch(void* const* d_in, const int* in_sizes, int n_in,
                              void* d_out, int out_size)
{
    (void)in_sizes; (void)n_in; (void)out_size;
    const float* query = (const float*)d_in[0];
    const float* key   = (const float*)d_in[1];
    const float* value = (const float*)d_in[2];
    const float* r     = (const float*)d_in[3];
    const int*   mask  = (const int*)  d_in[4];
    const float* Wq = (const float*)d_in[5];  const float* bq = (const float*)d_in[6];
    const float* Wk = (const float*)d_in[7];  const float* bk = (const float*)d_in[8];
    const float* Wv = (const float*)d_in[9];  const float* bv = (const float*)d_in[10];
    const float* Wr = (const float*)d_in[11]; const float* br = (const float*)d_in[12];

    float* out = (float*)d_out;                          // (B,H,S,DK)
    float* p   = out + (size_t)kBH * kS * kDK;           // (B,H,S,S)

    cudaFuncSetAttribute(proj_mma_kernel,
                         cudaFuncAttributeMaxDynamicSharedMemorySize, kPSmem);
    cudaFuncSetAttribute(scores_mma_kernel,
                         cudaFuncAttributeMaxDynamicSharedMemorySize, kSSmem);

    dim3 pgrid(kD / 128, kBS / 128, 3);                  // (8, 32, 3) merged
    proj_mma_kernel<<<pgrid, 256, kPSmem>>>(query, Wq, bq,
                                            key,   Wk, bk,
                                            r,     Wr, br,
                                            value, Wv, bv);

    dim3 sgrid(kS / 128, kBH);                           // (16, 32)
    scores_mma_kernel<<<sgrid, 256, kSSmem>>>(mask, p);

    dim3 ogrid(kS / 128, kBH);                           // (16, 32)
    out_kernel<<<ogrid, 256>>>(p, out);
}

// round 16
// speedup vs baseline: 1.0338x; 1.0338x over previous
#include <cuda_runtime.h>
#include <cstdint>

// ===========================================================================
// Problem constants
// ===========================================================================
namespace {
constexpr int kB  = 2;
constexpr int kS  = 2048;
constexpr int kD  = 1024;
constexpr int kH  = 16;
constexpr int kDK = 64;
constexpr int kBH = kB * kH;        // 32
constexpr int kBS = kB * kS;        // 4096
constexpr int kNRows = kBH * kS;    // 65536

// proj smem: Ah/Al/Bh/Bl [128 rows][36 floats]
constexpr int kPRS   = 36;
constexpr int kPTile = 128 * kPRS;
constexpr int kPSmem = 4 * kPTile * 4;             // 73728 bytes

// scores smem: Qh/Ql [128][68] + Kh/Kl [64][68]
constexpr int kQRS   = 68;
constexpr int kQTile = 128 * kQRS;
constexpr int kKTile = 64 * kQRS;
constexpr int kSSmem = (2 * kQTile + 2 * kKTile) * 4;   // 104448 bytes
}

// Scratch (allocation-free rule: __device__ globals)
__device__ float g_q [kBH * kS * kDK];   // 16 MB
__device__ float g_kr[kBH * kS * kDK];   // 16 MB (k_proj + r_proj)
__device__ float g_v [kBH * kS * kDK];   // 16 MB
__device__ float g_rinv[kNRows];

// ===========================================================================
// helpers (arch-neutral PTX, valid on sm_100 target)
// ===========================================================================
__device__ __forceinline__ void split_tf32(float x, uint32_t& hi, uint32_t& lo) {
    uint32_t h;
    asm("cvt.rna.tf32.f32 %0, %1;" : "=r"(h) : "f"(x));
    float lf = x - __uint_as_float(h);
    uint32_t l;
    asm("cvt.rna.tf32.f32 %0, %1;" : "=r"(l) : "f"(lf));
    hi = h; lo = l;
}

// D += A(tf32) * B(tf32); m16n8k8, A row-major, B col-major.
__device__ __forceinline__ void mma_m16n8k8_tf32(float* d, const uint32_t* a,
                                                 const uint32_t* b) {
    asm volatile(
        "mma.sync.aligned.m16n8k8.row.col.f32.tf32.tf32.f32 "
        "{%0,%1,%2,%3}, {%4,%5,%6,%7}, {%8,%9}, {%0,%1,%2,%3};"
        : "+f"(d[0]), "+f"(d[1]), "+f"(d[2]), "+f"(d[3])
        : "r"(a[0]), "r"(a[1]), "r"(a[2]), "r"(a[3]), "r"(b[0]), "r"(b[1]));
}

__device__ __forceinline__ void ldsm_x4(uint32_t* r, uint32_t saddr) {
    asm volatile("ldmatrix.sync.aligned.m8n8.x4.shared.b16 {%0,%1,%2,%3}, [%4];"
        : "=r"(r[0]), "=r"(r[1]), "=r"(r[2]), "=r"(r[3]) : "r"(saddr));
}
__device__ __forceinline__ void ldsm_x2(uint32_t* r, uint32_t saddr) {
    asm volatile("ldmatrix.sync.aligned.m8n8.x2.shared.b16 {%0,%1}, [%2];"
        : "=r"(r[0]), "=r"(r[1]) : "r"(saddr));
}
__device__ __forceinline__ uint32_t smem_u32(const void* p) {
    return (uint32_t)__cvta_generic_to_shared(p);
}

// ===========================================================================
// MERGED projection GEMM via mma.sync tf32x3 + ldmatrix.
// grid (D/128, BS/128, 3): z=0 -> q, z=1 -> kr (two passes), z=2 -> v.
// R16: __launch_bounds__(256,2) caps regs at 128 -> 2 CTAs/SM (was 136 regs,
// 1 CTA/SM, tensor 55%). Bias/dst selection deferred to epilogue to cut
// mainloop-live registers.
// ===========================================================================
__global__ __launch_bounds__(256, 2) void proj_mma_kernel(
    const float* __restrict__ query, const float* __restrict__ Wq, const float* __restrict__ bq,
    const float* __restrict__ key,   const float* __restrict__ Wk, const float* __restrict__ bk,
    const float* __restrict__ r,     const float* __restrict__ Wr, const float* __restrict__ br,
    const float* __restrict__ value, const float* __restrict__ Wv, const float* __restrict__ bv)
{
    extern __shared__ uint32_t smem_u[];
    uint32_t* Ah = smem_u;
    uint32_t* Al = smem_u + kPTile;
    uint32_t* Bh = smem_u + 2 * kPTile;
    uint32_t* Bl = smem_u + 3 * kPTile;
    const uint32_t ah_b = smem_u32(Ah), al_b = smem_u32(Al);
    const uint32_t bh_b = smem_u32(Bh), bl_b = smem_u32(Bl);

    const int zsel = blockIdx.z;
    // mainloop-live pointers only
    const float* X1; const float* W1;
    const float* X2 = nullptr; const float* W2 = nullptr;
    int ns;
    if (zsel == 0)      { X1 = query; W1 = Wq; ns = 32; }
    else if (zsel == 1) { X1 = key;   W1 = Wk; X2 = r; W2 = Wr; ns = 64; }
    else                { X1 = value; W1 = Wv; ns = 32; }

    const int tid   = threadIdx.x;
    const int wid   = tid >> 5;
    const int lane  = tid & 31;
    const int gid   = lane >> 2;
    const int tid4  = lane & 3;
    const int wm    = (wid >> 2) * 64;
    const int wn    = (wid & 3) * 32;
    const int m0    = blockIdx.y * 128;
    const int n0    = blockIdx.x * 128;

    const int a_row = lane & 15;
    const int a_ko  = ((lane >> 4) & 1) << 2;
    const int b_row = lane & 7;
    const int b_ko  = ((lane >> 3) & 1) << 2;

    float acc[4][4][4];
#pragma unroll
    for (int mt = 0; mt < 4; ++mt)
#pragma unroll
        for (int nt = 0; nt < 4; ++nt)
#pragma unroll
            for (int f = 0; f < 4; ++f) acc[mt][nt][f] = 0.f;

    for (int s = 0; s < ns; ++s) {
        const float* __restrict__ X = (s < 32) ? X1 : X2;
        const float* __restrict__ W = (s < 32) ? W1 : W2;
        const int k0 = (s & 31) * 32;

        float4 xa[4], wb[4];
#pragma unroll
        for (int i = 0; i < 4; ++i) {
            const int idx = tid + 256 * i;
            const int row = idx >> 3;
            const int c4  = (idx & 7) * 4;
            xa[i] = *reinterpret_cast<const float4*>(&X[(size_t)(m0 + row) * kD + k0 + c4]);
            wb[i] = *reinterpret_cast<const float4*>(&W[(size_t)(n0 + row) * kD + k0 + c4]);
        }
        __syncthreads();
#pragma unroll
        for (int i = 0; i < 4; ++i) {
            const int idx = tid + 256 * i;
            const int row = idx >> 3;
            const int c4  = (idx & 7) * 4;
            const float* xv = reinterpret_cast<const float*>(&xa[i]);
            const float* wv = reinterpret_cast<const float*>(&wb[i]);
#pragma unroll
            for (int j = 0; j < 4; ++j) {
                uint32_t h, l;
                split_tf32(xv[j], h, l);
                Ah[row * kPRS + c4 + j] = h;
                Al[row * kPRS + c4 + j] = l;
                split_tf32(wv[j], h, l);
                Bh[row * kPRS + c4 + j] = h;
                Bl[row * kPRS + c4 + j] = l;
            }
        }
        __syncthreads();

#pragma unroll
        for (int kk = 0; kk < 4; ++kk) {
            const int kb = kk * 8;

            uint32_t bhf[4][2], blf[4][2];
#pragma unroll
            for (int nt = 0; nt < 4; ++nt) {
                const uint32_t off =
                    (uint32_t)(((wn + nt * 8 + b_row) * kPRS + kb + b_ko) * 4);
                ldsm_x2(bhf[nt], bh_b + off);
                ldsm_x2(blf[nt], bl_b + off);
            }

#pragma unroll
            for (int mt = 0; mt < 4; ++mt) {
                const uint32_t off =
                    (uint32_t)(((wm + mt * 16 + a_row) * kPRS + kb + a_ko) * 4);
                uint32_t ah[4], al[4];
                ldsm_x4(ah, ah_b + off);
                ldsm_x4(al, al_b + off);
#pragma unroll
                for (int nt = 0; nt < 4; ++nt) {
                    mma_m16n8k8_tf32(acc[mt][nt], ah, bhf[nt]);
                    mma_m16n8k8_tf32(acc[mt][nt], ah, blf[nt]);
                    mma_m16n8k8_tf32(acc[mt][nt], al, bhf[nt]);
                }
            }
        }
    }

    // ---- epilogue: re-derive bias/dst from zsel (not mainloop-live) ----
    const float* __restrict__ b1 = (zsel == 0) ? bq : (zsel == 1) ? bk : bv;
    const float* __restrict__ b2 = (zsel == 1) ? br : nullptr;
    float* __restrict__ dst = (zsel == 0) ? g_q : (zsel == 1) ? g_kr : g_v;
#pragma unroll
    for (int nt = 0; nt < 4; ++nt) {
        const int e  = n0 + wn + nt * 8 + 2 * tid4;
        const int h  = e >> 6;
        const int dk = e & 63;
        float2 bb;
        bb.x = b1[e];     bb.y = b1[e + 1];
        if (b2) { bb.x += b2[e]; bb.y += b2[e + 1]; }
#pragma unroll
        for (int mt = 0; mt < 4; ++mt) {
#pragma unroll
            for (int half = 0; half < 2; ++half) {
                const int gm   = m0 + wm + mt * 16 + gid + half * 8;
                const int bidx = gm >> 11;
                const int srow = gm & (kS - 1);
                float2 o;
                o.x = acc[mt][nt][half * 2 + 0] + bb.x;
                o.y = acc[mt][nt][half * 2 + 1] + bb.y;
                *reinterpret_cast<float2*>(
                    &dst[(((size_t)bidx * kH + h) * kS + srow) * kDK + dk]) = o;
            }
        }
    }
}

// ===========================================================================
// Fused scores + softmax numerator + row sums via mma.sync tf32x3 + ldmatrix.
// (R11 verbatim, measured 489us)
// ===========================================================================
__global__ __launch_bounds__(256, 2) void scores_mma_kernel(const int* __restrict__ mask,
                                                            float* __restrict__ p)
{
    extern __shared__ uint32_t smem_u[];
    uint32_t* Qh = smem_u;
    uint32_t* Ql = smem_u + kQTile;
    uint32_t* Kh = smem_u + 2 * kQTile;
    uint32_t* Kl = smem_u + 2 * kQTile + kKTile;
    const uint32_t qh_b = smem_u32(Qh), ql_b = smem_u32(Ql);
    const uint32_t kh_b = smem_u32(Kh), kl_b = smem_u32(Kl);
    __shared__ float rs[128];

    const int tid   = threadIdx.x;
    const int wid   = tid >> 5;
    const int lane  = tid & 31;
    const int gid   = lane >> 2;
    const int tid4  = lane & 3;
    const int wm    = (wid >> 2) * 64;
    const int wn    = (wid & 3) * 16;
    const int bh    = blockIdx.y;
    const int m0    = blockIdx.x * 128;
    const int b_    = bh >> 4;
    const float scale = 0.125f;

    const int a_row = lane & 15;
    const int a_ko  = ((lane >> 4) & 1) << 2;
    const int b_row = lane & 7;
    const int b_ko  = ((lane >> 3) & 1) << 2;

    const float* __restrict__ Q  = g_q  + (size_t)bh * kS * kDK;
    const float* __restrict__ KR = g_kr + (size_t)bh * kS * kDK;

    if (tid < 128) rs[tid] = 0.f;

    for (int i = tid; i < 128 * 16; i += 256) {
        const int row = i >> 4;
        const int kq  = (i & 15) * 4;
        float4 v = *reinterpret_cast<const float4*>(&Q[(size_t)(m0 + row) * kDK + kq]);
        const float* vv = reinterpret_cast<const float*>(&v);
#pragma unroll
        for (int j = 0; j < 4; ++j) {
            uint32_t h, l;
            split_tf32(vv[j], h, l);
            Qh[row * kQRS + kq + j] = h;
            Ql[row * kQRS + kq + j] = l;
        }
    }

    float rsum[4][2];
#pragma unroll
    for (int mt = 0; mt < 4; ++mt) { rsum[mt][0] = 0.f; rsum[mt][1] = 0.f; }

    for (int nb = 0; nb < kS; nb += 64) {
        __syncthreads();
        for (int i = tid; i < 64 * 16; i += 256) {
            const int n  = i >> 4;
            const int kq = (i & 15) * 4;
            float4 v = *reinterpret_cast<const float4*>(&KR[(size_t)(nb + n) * kDK + kq]);
            const float* vv = reinterpret_cast<const float*>(&v);
#pragma unroll
            for (int j = 0; j < 4; ++j) {
                uint32_t h, l;
                split_tf32(vv[j], h, l);
                Kh[n * kQRS + kq + j] = h;
                Kl[n * kQRS + kq + j] = l;
            }
        }
        __syncthreads();

        float acc[4][2][4];
#pragma unroll
        for (int mt = 0; mt < 4; ++mt)
#pragma unroll
            for (int nt = 0; nt < 2; ++nt)
#pragma unroll
                for (int f = 0; f < 4; ++f) acc[mt][nt][f] = 0.f;

#pragma unroll
        for (int kk = 0; kk < 8; ++kk) {
            const int kb = kk * 8;

            uint32_t bhf[2][2], blf[2][2];
#pragma unroll
            for (int nt = 0; nt < 2; ++nt) {
                const uint32_t off =
                    (uint32_t)(((wn + nt * 8 + b_row) * kQRS + kb + b_ko) * 4);
                ldsm_x2(bhf[nt], kh_b + off);
                ldsm_x2(blf[nt], kl_b + off);
            }

#pragma unroll
            for (int mt = 0; mt < 4; ++mt) {
                const uint32_t off =
                    (uint32_t)(((wm + mt * 16 + a_row) * kQRS + kb + a_ko) * 4);
                uint32_t ah[4], al[4];
                ldsm_x4(ah, qh_b + off);
                ldsm_x4(al, ql_b + off);
#pragma unroll
                for (int nt = 0; nt < 2; ++nt) {
                    mma_m16n8k8_tf32(acc[mt][nt], ah, bhf[nt]);
                    mma_m16n8k8_tf32(acc[mt][nt], ah, blf[nt]);
                    mma_m16n8k8_tf32(acc[mt][nt], al, bhf[nt]);
                }
            }
        }

#pragma unroll
        for (int mt = 0; mt < 4; ++mt) {
#pragma unroll
            for (int nt = 0; nt < 2; ++nt) {
                const int sk = nb + wn + nt * 8 + 2 * tid4;
#pragma unroll
                for (int half = 0; half < 2; ++half) {
                    const int sq = m0 + wm + mt * 16 + gid + half * 8;
                    int2 mm = *reinterpret_cast<const int2*>(
                        &mask[((size_t)b_ * kS + sq) * kS + sk]);
                    const float f0 = acc[mt][nt][half * 2 + 0] * scale;
                    const float f1 = acc[mt][nt][half * 2 + 1] * scale;
                    float2 e;
                    e.x = mm.x ? __expf(f0) : 0.f;
                    e.y = mm.y ? __expf(f1) : 0.f;
                    *reinterpret_cast<float2*>(
                        &p[((size_t)bh * kS + sq) * kS + sk]) = e;
                    rsum[mt][half] += e.x + e.y;
                }
            }
        }
    }

    __syncthreads();
#pragma unroll
    for (int mt = 0; mt < 4; ++mt) {
#pragma unroll
        for (int half = 0; half < 2; ++half) {
            float s = rsum[mt][half];
            s += __shfl_xor_sync(0xffffffffu, s, 1);
            s += __shfl_xor_sync(0xffffffffu, s, 2);
            if (tid4 == 0)
                atomicAdd(&rs[wm + mt * 16 + gid + half * 8], s);
        }
    }
    __syncthreads();
    if (tid < 128) g_rinv[bh * kS + m0 + tid] = 1.0f / rs[tid];
}

// ===========================================================================
// out = p @ v with on-the-fly normalization; writes final p back.
// R8 version verbatim (measured ~453us; best of 4 variants tried).
// ===========================================================================
__global__ __launch_bounds__(256, 2) void out_kernel(float* __restrict__ p,
                                                     float* __restrict__ out)
{
    __shared__ float As[16][128];
    __shared__ float Bs[16][64];
    __shared__ float s_inv[128];

    const int bh  = blockIdx.y;
    const int m0  = blockIdx.x * 128;
    const int tid = threadIdx.x;
    const int tx  = tid & 15;
    const int ty  = tid >> 4;

    if (tid < 128) {
        s_inv[tid] = g_rinv[bh * kS + m0 + tid];
    }
    __syncthreads();

    float acc[8][4];
#pragma unroll
    for (int i = 0; i < 8; ++i)
#pragma unroll
        for (int j = 0; j < 4; ++j) acc[i][j] = 0.f;

    float* __restrict__ prow = p + (size_t)bh * kS * kS + (size_t)m0 * kS;
    const float* __restrict__ V = g_v + (size_t)bh * kS * kDK;

    const int r0 = tid >> 2;
    const int c0 = (tid & 3) * 4;
    const int vk = tid >> 4;
    const int vn = (tid & 15) * 4;

    const float iv0 = s_inv[r0];
    const float iv1 = s_inv[r0 + 64];

    for (int k0 = 0; k0 < kS; k0 += 16) {
        float4 x0 = *reinterpret_cast<const float4*>(&prow[(size_t)r0 * kS + k0 + c0]);
        float4 x1 = *reinterpret_cast<const float4*>(&prow[(size_t)(r0 + 64) * kS + k0 + c0]);
        float4 n0v, n1v;
        n0v.x = x0.x * iv0;  n0v.y = x0.y * iv0;
        n0v.z = x0.z * iv0;  n0v.w = x0.w * iv0;
        n1v.x = x1.x * iv1;  n1v.y = x1.y * iv1;
        n1v.z = x1.z * iv1;  n1v.w = x1.w * iv1;

        float4 vb = *reinterpret_cast<const float4*>(&V[(k0 + vk) * kDK + vn]);

        __syncthreads();
        As[c0 + 0][r0]      = n0v.x; As[c0 + 1][r0]      = n0v.y;
        As[c0 + 2][r0]      = n0v.z; As[c0 + 3][r0]      = n0v.w;
        As[c0 + 0][r0 + 64] = n1v.x; As[c0 + 1][r0 + 64] = n1v.y;
        As[c0 + 2][r0 + 64] = n1v.z; As[c0 + 3][r0 + 64] = n1v.w;
        *reinterpret_cast<float4*>(&Bs[vk][vn]) = vb;

        *reinterpret_cast<float4*>(&prow[(size_t)r0 * kS + k0 + c0])        = n0v;
        *reinterpret_cast<float4*>(&prow[(size_t)(r0 + 64) * kS + k0 + c0]) = n1v;
        __syncthreads();

#pragma unroll
        for (int kk = 0; kk < 16; ++kk) {
            float4 a0 = *reinterpret_cast<const float4*>(&As[kk][ty * 8]);
            float4 a1 = *reinterpret_cast<const float4*>(&As[kk][ty * 8 + 4]);
            float4 bb = *reinterpret_cast<const float4*>(&Bs[kk][tx * 4]);
            float a[8]  = {a0.x, a0.y, a0.z, a0.w, a1.x, a1.y, a1.z, a1.w};
            float bj[4] = {bb.x, bb.y, bb.z, bb.w};
#pragma unroll
            for (int i = 0; i < 8; ++i)
#pragma unroll
                for (int j = 0; j < 4; ++j) acc[i][j] += a[i] * bj[j];
        }
    }

    float* __restrict__ orow = out + (size_t)bh * kS * kDK;
#pragma unroll
    for (int i = 0; i < 8; ++i) {
        float4 o = make_float4(acc[i][0], acc[i][1], acc[i][2], acc[i][3]);
        *reinterpret_cast<float4*>(&orow[(m0 + ty * 8 + i) * kDK + tx * 4]) = o;
    }
}

// ===========================================================================
extern "C" void kernel_launch(void* const* d_in, const int* in_sizes, int n_in,
                              void* d_out, int out_size)
{
    (void)in_sizes; (void)n_in; (void)out_size;
    const float* query = (const float*)d_in[0];
    const float* key   = (const float*)d_in[1];
    const float* value = (const float*)d_in[2];
    const float* r     = (const float*)d_in[3];
    const int*   mask  = (const int*)  d_in[4];
    const float* Wq = (const float*)d_in[5];  const float* bq = (const float*)d_in[6];
    const float* Wk = (const float*)d_in[7];  const float* bk = (const float*)d_in[8];
    const float* Wv = (const float*)d_in[9];  const float* bv = (const float*)d_in[10];
    const float* Wr = (const float*)d_in[11]; const float* br = (const float*)d_in[12];

    float* out = (float*)d_out;                          // (B,H,S,DK)
    float* p   = out + (size_t)kBH * kS * kDK;           // (B,H,S,S)

    cudaFuncSetAttribute(proj_mma_kernel,
                         cudaFuncAttributeMaxDynamicSharedMemorySize, kPSmem);
    cudaFuncSetAttribute(scores_mma_kernel,
                         cudaFuncAttributeMaxDynamicSharedMemorySize, kSSmem);

    dim3 pgrid(kD / 128, kBS / 128, 3);                  // (8, 32, 3) merged
    proj_mma_kernel<<<pgrid, 256, kPSmem>>>(query, Wq, bq,
                                            key,   Wk, bk,
                                            r,     Wr, br,
                                            value, Wv, bv);

    dim3 sgrid(kS / 128, kBH);                           // (16, 32)
    scores_mma_kernel<<<sgrid, 256, kSSmem>>>(mask, p);

    dim3 ogrid(kS / 128, kBH);                           // (16, 32)
    out_kernel<<<ogrid, 256>>>(p, out);
}

// round 17
// speedup vs baseline: 1.3089x; 1.2660x over previous
#include <cuda_runtime.h>
#include <cuda_fp16.h>
#include <cstdint>

// ===========================================================================
// Problem constants
// ===========================================================================
namespace {
constexpr int kB  = 2;
constexpr int kS  = 2048;
constexpr int kD  = 1024;
constexpr int kH  = 16;
constexpr int kDK = 64;
constexpr int kBH = kB * kH;        // 32
constexpr int kBS = kB * kS;        // 4096
constexpr int kNRows = kBH * kS;    // 65536

// proj smem (fp16): Ah/Al/Bh/Bl [128 rows][40 fp16]  (stride 40: 80B = 20
// words; rows land on banks 0,20,8,28,16,4,24,12 -> conflict-free ldmatrix)
constexpr int kPRS   = 40;                          // fp16 units
constexpr int kPTile = 128 * kPRS;                  // fp16 elems per tile
constexpr int kPSmem = 4 * kPTile * 2;              // 40960 bytes

// scores smem (fp16): Qh/Ql [128][72] + Kh/Kl [64][72]  (stride 72: 144B =
// 36 words; rows at +4 banks -> conflict-free)
constexpr int kQRS   = 72;
constexpr int kQTile = 128 * kQRS;
constexpr int kKTile = 64 * kQRS;
constexpr int kSSmem = (2 * kQTile + 2 * kKTile) * 2;   // 55296 bytes
}

// Scratch (allocation-free rule: __device__ globals)
__device__ float g_q [kBH * kS * kDK];   // 16 MB
__device__ float g_kr[kBH * kS * kDK];   // 16 MB (k_proj + r_proj)
__device__ float g_v [kBH * kS * kDK];   // 16 MB
__device__ float g_rinv[kNRows];

// ===========================================================================
// helpers (arch-neutral PTX, valid on sm_100 target)
// ===========================================================================

// split two fp32 into packed fp16 hi-pair and lo-pair (x -> low 16 bits)
__device__ __forceinline__ void split_h2(float a, float b,
                                         uint32_t& hp, uint32_t& lp) {
    __half2 h = __floats2half2_rn(a, b);
    float2 hf = __half22float2(h);
    __half2 l = __floats2half2_rn(a - hf.x, b - hf.y);
    hp = *reinterpret_cast<uint32_t*>(&h);
    lp = *reinterpret_cast<uint32_t*>(&l);
}

// D += A(f16) * B(f16); m16n8k16, A row-major, B col-major, fp32 accum.
__device__ __forceinline__ void mma_m16n8k16_f16(float* d, const uint32_t* a,
                                                 const uint32_t* b) {
    asm volatile(
        "mma.sync.aligned.m16n8k16.row.col.f32.f16.f16.f32 "
        "{%0,%1,%2,%3}, {%4,%5,%6,%7}, {%8,%9}, {%0,%1,%2,%3};"
        : "+f"(d[0]), "+f"(d[1]), "+f"(d[2]), "+f"(d[3])
        : "r"(a[0]), "r"(a[1]), "r"(a[2]), "r"(a[3]), "r"(b[0]), "r"(b[1]));
}

__device__ __forceinline__ void ldsm_x4(uint32_t* r, uint32_t saddr) {
    asm volatile("ldmatrix.sync.aligned.m8n8.x4.shared.b16 {%0,%1,%2,%3}, [%4];"
        : "=r"(r[0]), "=r"(r[1]), "=r"(r[2]), "=r"(r[3]) : "r"(saddr));
}
__device__ __forceinline__ void ldsm_x2(uint32_t* r, uint32_t saddr) {
    asm volatile("ldmatrix.sync.aligned.m8n8.x2.shared.b16 {%0,%1}, [%2];"
        : "=r"(r[0]), "=r"(r[1]) : "r"(saddr));
}
__device__ __forceinline__ uint32_t smem_u32(const void* p) {
    return (uint32_t)__cvta_generic_to_shared(p);
}

// ===========================================================================
// MERGED projection GEMM via mma.sync fp16x2 + ldmatrix.
// grid (D/128, BS/128, 3): z=0 -> q, z=1 -> kr (two passes), z=2 -> v.
// K=16 per mma (was 8 with tf32) -> tensor & ldsm work halved.
// ===========================================================================
__global__ __launch_bounds__(256, 2) void proj_mma_kernel(
    const float* __restrict__ query, const float* __restrict__ Wq, const float* __restrict__ bq,
    const float* __restrict__ key,   const float* __restrict__ Wk, const float* __restrict__ bk,
    const float* __restrict__ r,     const float* __restrict__ Wr, const float* __restrict__ br,
    const float* __restrict__ value, const float* __restrict__ Wv, const float* __restrict__ bv)
{
    extern __shared__ uint16_t smem_h[];
    uint16_t* Ah = smem_h;
    uint16_t* Al = smem_h + kPTile;
    uint16_t* Bh = smem_h + 2 * kPTile;
    uint16_t* Bl = smem_h + 3 * kPTile;
    const uint32_t ah_b = smem_u32(Ah), al_b = smem_u32(Al);
    const uint32_t bh_b = smem_u32(Bh), bl_b = smem_u32(Bl);

    const int zsel = blockIdx.z;
    const float* X1; const float* W1;
    const float* X2 = nullptr; const float* W2 = nullptr;
    int ns;
    if (zsel == 0)      { X1 = query; W1 = Wq; ns = 32; }
    else if (zsel == 1) { X1 = key;   W1 = Wk; X2 = r; W2 = Wr; ns = 64; }
    else                { X1 = value; W1 = Wv; ns = 32; }

    const int tid   = threadIdx.x;
    const int wid   = tid >> 5;
    const int lane  = tid & 31;
    const int gid   = lane >> 2;
    const int tid4  = lane & 3;
    const int wm    = (wid >> 2) * 64;
    const int wn    = (wid & 3) * 32;
    const int m0    = blockIdx.y * 128;
    const int n0    = blockIdx.x * 128;

    // ldmatrix per-lane offsets (fp16 units)
    const int a_row = lane & 15;
    const int a_ko  = ((lane >> 4) & 1) << 3;   // 0 / 8 fp16 = 0/16B
    const int b_row = lane & 7;
    const int b_ko  = ((lane >> 3) & 1) << 3;

    float acc[4][4][4];
#pragma unroll
    for (int mt = 0; mt < 4; ++mt)
#pragma unroll
        for (int nt = 0; nt < 4; ++nt)
#pragma unroll
            for (int f = 0; f < 4; ++f) acc[mt][nt][f] = 0.f;

    for (int s = 0; s < ns; ++s) {
        const float* __restrict__ X = (s < 32) ? X1 : X2;
        const float* __restrict__ W = (s < 32) ? W1 : W2;
        const int k0 = (s & 31) * 32;

        float4 xa[4], wb[4];
#pragma unroll
        for (int i = 0; i < 4; ++i) {
            const int idx = tid + 256 * i;
            const int row = idx >> 3;
            const int c4  = (idx & 7) * 4;
            xa[i] = *reinterpret_cast<const float4*>(&X[(size_t)(m0 + row) * kD + k0 + c4]);
            wb[i] = *reinterpret_cast<const float4*>(&W[(size_t)(n0 + row) * kD + k0 + c4]);
        }
        __syncthreads();
#pragma unroll
        for (int i = 0; i < 4; ++i) {
            const int idx = tid + 256 * i;
            const int row = idx >> 3;
            const int c4  = (idx & 7) * 4;
            uint2 hp, lp;
            split_h2(xa[i].x, xa[i].y, hp.x, lp.x);
            split_h2(xa[i].z, xa[i].w, hp.y, lp.y);
            *reinterpret_cast<uint2*>(&Ah[row * kPRS + c4]) = hp;
            *reinterpret_cast<uint2*>(&Al[row * kPRS + c4]) = lp;
            split_h2(wb[i].x, wb[i].y, hp.x, lp.x);
            split_h2(wb[i].z, wb[i].w, hp.y, lp.y);
            *reinterpret_cast<uint2*>(&Bh[row * kPRS + c4]) = hp;
            *reinterpret_cast<uint2*>(&Bl[row * kPRS + c4]) = lp;
        }
        __syncthreads();

#pragma unroll
        for (int kk = 0; kk < 2; ++kk) {        // K=16 per step
            const int kb = kk * 16;

            uint32_t bhf[4][2], blf[4][2];
#pragma unroll
            for (int nt = 0; nt < 4; ++nt) {
                const uint32_t off =
                    (uint32_t)(((wn + nt * 8 + b_row) * kPRS + kb + b_ko) * 2);
                ldsm_x2(bhf[nt], bh_b + off);
                ldsm_x2(blf[nt], bl_b + off);
            }

#pragma unroll
            for (int mt = 0; mt < 4; ++mt) {
                const uint32_t off =
                    (uint32_t)(((wm + mt * 16 + a_row) * kPRS + kb + a_ko) * 2);
                uint32_t ah[4], al[4];
                ldsm_x4(ah, ah_b + off);
                ldsm_x4(al, al_b + off);
#pragma unroll
                for (int nt = 0; nt < 4; ++nt) {
                    mma_m16n8k16_f16(acc[mt][nt], ah, bhf[nt]);
                    mma_m16n8k16_f16(acc[mt][nt], ah, blf[nt]);
                    mma_m16n8k16_f16(acc[mt][nt], al, bhf[nt]);
                }
            }
        }
    }

    // ---- epilogue: re-derive bias/dst from zsel ----
    const float* __restrict__ b1 = (zsel == 0) ? bq : (zsel == 1) ? bk : bv;
    const float* __restrict__ b2 = (zsel == 1) ? br : nullptr;
    float* __restrict__ dst = (zsel == 0) ? g_q : (zsel == 1) ? g_kr : g_v;
#pragma unroll
    for (int nt = 0; nt < 4; ++nt) {
        const int e  = n0 + wn + nt * 8 + 2 * tid4;
        const int h  = e >> 6;
        const int dk = e & 63;
        float2 bb;
        bb.x = b1[e];     bb.y = b1[e + 1];
        if (b2) { bb.x += b2[e]; bb.y += b2[e + 1]; }
#pragma unroll
        for (int mt = 0; mt < 4; ++mt) {
#pragma unroll
            for (int half = 0; half < 2; ++half) {
                const int gm   = m0 + wm + mt * 16 + gid + half * 8;
                const int bidx = gm >> 11;
                const int srow = gm & (kS - 1);
                float2 o;
                o.x = acc[mt][nt][half * 2 + 0] + bb.x;
                o.y = acc[mt][nt][half * 2 + 1] + bb.y;
                *reinterpret_cast<float2*>(
                    &dst[(((size_t)bidx * kH + h) * kS + srow) * kDK + dk]) = o;
            }
        }
    }
}

// ===========================================================================
// Fused scores + softmax numerator + row sums via mma.sync fp16x2 + ldmatrix.
//   e = mask ? exp(q@kr^T * scale) : 0 -> p;  g_rinv = 1/rowsum
// ===========================================================================
__global__ __launch_bounds__(256, 2) void scores_mma_kernel(const int* __restrict__ mask,
                                                            float* __restrict__ p)
{
    extern __shared__ uint16_t smem_h[];
    uint16_t* Qh = smem_h;
    uint16_t* Ql = smem_h + kQTile;
    uint16_t* Kh = smem_h + 2 * kQTile;
    uint16_t* Kl = smem_h + 2 * kQTile + kKTile;
    const uint32_t qh_b = smem_u32(Qh), ql_b = smem_u32(Ql);
    const uint32_t kh_b = smem_u32(Kh), kl_b = smem_u32(Kl);
    __shared__ float rs[128];

    const int tid   = threadIdx.x;
    const int wid   = tid >> 5;
    const int lane  = tid & 31;
    const int gid   = lane >> 2;
    const int tid4  = lane & 3;
    const int wm    = (wid >> 2) * 64;
    const int wn    = (wid & 3) * 16;
    const int bh    = blockIdx.y;
    const int m0    = blockIdx.x * 128;
    const int b_    = bh >> 4;
    const float scale = 0.125f;

    const int a_row = lane & 15;
    const int a_ko  = ((lane >> 4) & 1) << 3;
    const int b_row = lane & 7;
    const int b_ko  = ((lane >> 3) & 1) << 3;

    const float* __restrict__ Q  = g_q  + (size_t)bh * kS * kDK;
    const float* __restrict__ KR = g_kr + (size_t)bh * kS * kDK;

    if (tid < 128) rs[tid] = 0.f;

    // ---- load + split Q strip (128 x 64) ----
    for (int i = tid; i < 128 * 16; i += 256) {
        const int row = i >> 4;
        const int kq  = (i & 15) * 4;
        float4 v = *reinterpret_cast<const float4*>(&Q[(size_t)(m0 + row) * kDK + kq]);
        uint2 hp, lp;
        split_h2(v.x, v.y, hp.x, lp.x);
        split_h2(v.z, v.w, hp.y, lp.y);
        *reinterpret_cast<uint2*>(&Qh[row * kQRS + kq]) = hp;
        *reinterpret_cast<uint2*>(&Ql[row * kQRS + kq]) = lp;
    }

    float rsum[4][2];
#pragma unroll
    for (int mt = 0; mt < 4; ++mt) { rsum[mt][0] = 0.f; rsum[mt][1] = 0.f; }

    for (int nb = 0; nb < kS; nb += 64) {
        __syncthreads();
        for (int i = tid; i < 64 * 16; i += 256) {
            const int n  = i >> 4;
            const int kq = (i & 15) * 4;
            float4 v = *reinterpret_cast<const float4*>(&KR[(size_t)(nb + n) * kDK + kq]);
            uint2 hp, lp;
            split_h2(v.x, v.y, hp.x, lp.x);
            split_h2(v.z, v.w, hp.y, lp.y);
            *reinterpret_cast<uint2*>(&Kh[n * kQRS + kq]) = hp;
            *reinterpret_cast<uint2*>(&Kl[n * kQRS + kq]) = lp;
        }
        __syncthreads();

        float acc[4][2][4];
#pragma unroll
        for (int mt = 0; mt < 4; ++mt)
#pragma unroll
            for (int nt = 0; nt < 2; ++nt)
#pragma unroll
                for (int f = 0; f < 4; ++f) acc[mt][nt][f] = 0.f;

#pragma unroll
        for (int kk = 0; kk < 4; ++kk) {        // K=16 per step over DK=64
            const int kb = kk * 16;

            uint32_t bhf[2][2], blf[2][2];
#pragma unroll
            for (int nt = 0; nt < 2; ++nt) {
                const uint32_t off =
                    (uint32_t)(((wn + nt * 8 + b_row) * kQRS + kb + b_ko) * 2);
                ldsm_x2(bhf[nt], kh_b + off);
                ldsm_x2(blf[nt], kl_b + off);
            }

#pragma unroll
            for (int mt = 0; mt < 4; ++mt) {
                const uint32_t off =
                    (uint32_t)(((wm + mt * 16 + a_row) * kQRS + kb + a_ko) * 2);
                uint32_t ah[4], al[4];
                ldsm_x4(ah, qh_b + off);
                ldsm_x4(al, ql_b + off);
#pragma unroll
                for (int nt = 0; nt < 2; ++nt) {
                    mma_m16n8k16_f16(acc[mt][nt], ah, bhf[nt]);
                    mma_m16n8k16_f16(acc[mt][nt], ah, blf[nt]);
                    mma_m16n8k16_f16(acc[mt][nt], al, bhf[nt]);
                }
            }
        }

        // ---- epilogue: mask -> exp -> store numerators -> row partials ----
#pragma unroll
        for (int mt = 0; mt < 4; ++mt) {
#pragma unroll
            for (int nt = 0; nt < 2; ++nt) {
                const int sk = nb + wn + nt * 8 + 2 * tid4;
#pragma unroll
                for (int half = 0; half < 2; ++half) {
                    const int sq = m0 + wm + mt * 16 + gid + half * 8;
                    int2 mm = *reinterpret_cast<const int2*>(
                        &mask[((size_t)b_ * kS + sq) * kS + sk]);
                    const float f0 = acc[mt][nt][half * 2 + 0] * scale;
                    const float f1 = acc[mt][nt][half * 2 + 1] * scale;
                    float2 e;
                    e.x = mm.x ? __expf(f0) : 0.f;
                    e.y = mm.y ? __expf(f1) : 0.f;
                    *reinterpret_cast<float2*>(
                        &p[((size_t)bh * kS + sq) * kS + sk]) = e;
                    rsum[mt][half] += e.x + e.y;
                }
            }
        }
    }

    __syncthreads();
#pragma unroll
    for (int mt = 0; mt < 4; ++mt) {
#pragma unroll
        for (int half = 0; half < 2; ++half) {
            float s = rsum[mt][half];
            s += __shfl_xor_sync(0xffffffffu, s, 1);
            s += __shfl_xor_sync(0xffffffffu, s, 2);
            if (tid4 == 0)
                atomicAdd(&rs[wm + mt * 16 + gid + half * 8], s);
        }
    }
    __syncthreads();
    if (tid < 128) g_rinv[bh * kS + m0 + tid] = 1.0f / rs[tid];
}

// ===========================================================================
// out = p @ v with on-the-fly normalization; writes final p back.
// R8 version verbatim (measured ~453us; best of variants tried).
// ===========================================================================
__global__ __launch_bounds__(256, 2) void out_kernel(float* __restrict__ p,
                                                     float* __restrict__ out)
{
    __shared__ float As[16][128];
    __shared__ float Bs[16][64];
    __shared__ float s_inv[128];

    const int bh  = blockIdx.y;
    const int m0  = blockIdx.x * 128;
    const int tid = threadIdx.x;
    const int tx  = tid & 15;
    const int ty  = tid >> 4;

    if (tid < 128) {
        s_inv[tid] = g_rinv[bh * kS + m0 + tid];
    }
    __syncthreads();

    float acc[8][4];
#pragma unroll
    for (int i = 0; i < 8; ++i)
#pragma unroll
        for (int j = 0; j < 4; ++j) acc[i][j] = 0.f;

    float* __restrict__ prow = p + (size_t)bh * kS * kS + (size_t)m0 * kS;
    const float* __restrict__ V = g_v + (size_t)bh * kS * kDK;

    const int r0 = tid >> 2;
    const int c0 = (tid & 3) * 4;
    const int vk = tid >> 4;
    const int vn = (tid & 15) * 4;

    const float iv0 = s_inv[r0];
    const float iv1 = s_inv[r0 + 64];

    for (int k0 = 0; k0 < kS; k0 += 16) {
        float4 x0 = *reinterpret_cast<const float4*>(&prow[(size_t)r0 * kS + k0 + c0]);
        float4 x1 = *reinterpret_cast<const float4*>(&prow[(size_t)(r0 + 64) * kS + k0 + c0]);
        float4 n0v, n1v;
        n0v.x = x0.x * iv0;  n0v.y = x0.y * iv0;
        n0v.z = x0.z * iv0;  n0v.w = x0.w * iv0;
        n1v.x = x1.x * iv1;  n1v.y = x1.y * iv1;
        n1v.z = x1.z * iv1;  n1v.w = x1.w * iv1;

        float4 vb = *reinterpret_cast<const float4*>(&V[(k0 + vk) * kDK + vn]);

        __syncthreads();
        As[c0 + 0][r0]      = n0v.x; As[c0 + 1][r0]      = n0v.y;
        As[c0 + 2][r0]      = n0v.z; As[c0 + 3][r0]      = n0v.w;
        As[c0 + 0][r0 + 64] = n1v.x; As[c0 + 1][r0 + 64] = n1v.y;
        As[c0 + 2][r0 + 64] = n1v.z; As[c0 + 3][r0 + 64] = n1v.w;
        *reinterpret_cast<float4*>(&Bs[vk][vn]) = vb;

        *reinterpret_cast<float4*>(&prow[(size_t)r0 * kS + k0 + c0])        = n0v;
        *reinterpret_cast<float4*>(&prow[(size_t)(r0 + 64) * kS + k0 + c0]) = n1v;
        __syncthreads();

#pragma unroll
        for (int kk = 0; kk < 16; ++kk) {
            float4 a0 = *reinterpret_cast<const float4*>(&As[kk][ty * 8]);
            float4 a1 = *reinterpret_cast<const float4*>(&As[kk][ty * 8 + 4]);
            float4 bb = *reinterpret_cast<const float4*>(&Bs[kk][tx * 4]);
            float a[8]  = {a0.x, a0.y, a0.z, a0.w, a1.x, a1.y, a1.z, a1.w};
            float bj[4] = {bb.x, bb.y, bb.z, bb.w};
#pragma unroll
            for (int i = 0; i < 8; ++i)
#pragma unroll
                for (int j = 0; j < 4; ++j) acc[i][j] += a[i] * bj[j];
        }
    }

    float* __restrict__ orow = out + (size_t)bh * kS * kDK;
#pragma unroll
    for (int i = 0; i < 8; ++i) {
        float4 o = make_float4(acc[i][0], acc[i][1], acc[i][2], acc[i][3]);
        *reinterpret_cast<float4*>(&orow[(m0 + ty * 8 + i) * kDK + tx * 4]) = o;
    }
}

// ===========================================================================
extern "C" void kernel_launch(void* const* d_in, const int* in_sizes, int n_in,
                              void* d_out, int out_size)
{
    (void)in_sizes; (void)n_in; (void)out_size;
    const float* query = (const float*)d_in[0];
    const float* key   = (const float*)d_in[1];
    const float* value = (const float*)d_in[2];
    const float* r     = (const float*)d_in[3];
    const int*   mask  = (const int*)  d_in[4];
    const float* Wq = (const float*)d_in[5];  const float* bq = (const float*)d_in[6];
    const float* Wk = (const float*)d_in[7];  const float* bk = (const float*)d_in[8];
    const float* Wv = (const float*)d_in[9];  const float* bv = (const float*)d_in[10];
    const float* Wr = (const float*)d_in[11]; const float* br = (const float*)d_in[12];

    float* out = (float*)d_out;                          // (B,H,S,DK)
    float* p   = out + (size_t)kBH * kS * kDK;           // (B,H,S,S)

    cudaFuncSetAttribute(proj_mma_kernel,
                         cudaFuncAttributeMaxDynamicSharedMemorySize, kPSmem);
    cudaFuncSetAttribute(scores_mma_kernel,
                         cudaFuncAttributeMaxDynamicSharedMemorySize, kSSmem);

    dim3 pgrid(kD / 128, kBS / 128, 3);                  // (8, 32, 3) merged
    proj_mma_kernel<<<pgrid, 256, kPSmem>>>(query, Wq, bq,
                                            key,   Wk, bk,
                                            r,     Wr, br,
                                            value, Wv, bv);

    dim3 sgrid(kS / 128, kBH);                           // (16, 32)
    scores_mma_kernel<<<sgrid, 256, kSSmem>>>(mask, p);

    dim3 ogrid(kS / 128, kBH);                           // (16, 32)
    out_kernel<<<ogrid, 256>>>(p, out);
}